// round 1
// baseline (speedup 1.0000x reference)
#include <cuda_runtime.h>
#include <cstdint>

// Problem constants
constexpr int Bsz = 4;
constexpr int Sq  = 2048;
constexpr int Dm  = 1024;

// Scratch (device globals: no allocation allowed)
__device__ float g_Q[(long)Bsz * Sq * Dm];
__device__ float g_K[(long)Bsz * Sq * Dm];
__device__ float g_V[(long)Bsz * Sq * Dm];
__device__ float g_P[(long)Bsz * Sq * Sq];   // scores, then probabilities in-place

// ---------------------------------------------------------------------------
// helpers
// ---------------------------------------------------------------------------
__device__ __forceinline__ void cp_async16(void* smem, const void* gmem) {
    uint32_t s = (uint32_t)__cvta_generic_to_shared(smem);
    asm volatile("cp.async.cg.shared.global [%0], [%1], 16;\n" :: "r"(s), "l"(gmem));
}
__device__ __forceinline__ void cp_commit() { asm volatile("cp.async.commit_group;\n"); }
__device__ __forceinline__ void cp_wait1()  { asm volatile("cp.async.wait_group 1;\n"); }
__device__ __forceinline__ void cp_wait0()  { asm volatile("cp.async.wait_group 0;\n"); }

__device__ __forceinline__ uint32_t f2tf32(float f) {
    uint32_t r;
    asm("cvt.rna.tf32.f32 %0, %1;" : "=r"(r) : "f"(f));
    return r;
}

__device__ __forceinline__ void mma_tf32(float* d, const uint32_t* a, const uint32_t* b) {
    asm volatile(
        "mma.sync.aligned.m16n8k8.row.col.f32.tf32.tf32.f32 "
        "{%0,%1,%2,%3},{%4,%5,%6,%7},{%8,%9},{%0,%1,%2,%3};"
        : "+f"(d[0]), "+f"(d[1]), "+f"(d[2]), "+f"(d[3])
        : "r"(a[0]), "r"(a[1]), "r"(a[2]), "r"(a[3]), "r"(b[0]), "r"(b[1]));
}

__device__ __forceinline__ float warp_max(float v) {
    #pragma unroll
    for (int o = 16; o; o >>= 1) v = fmaxf(v, __shfl_xor_sync(0xFFFFFFFFu, v, o));
    return v;
}
__device__ __forceinline__ float warp_sum(float v) {
    #pragma unroll
    for (int o = 16; o; o >>= 1) v += __shfl_xor_sync(0xFFFFFFFFu, v, o);
    return v;
}

// ---------------------------------------------------------------------------
// Generic TF32 tensor-core GEMM: C[M,N] = A[M,K] * B (NN) or A * B^T (NT)
// Tile: 64 (M) x 128 (N) x 16 (K).  256 threads = 8 warps in 2x4 (m x n),
// warp tile 32x32 = 2x4 m16n8k8 mma tiles.
// TRANS_B:    B is [N,K] row-major (scores: Q @ K^T)
// CAUSAL_SKIP: skip CTAs fully above the diagonal (scores)
// KLIMIT:     K-loop limit = m0+64 (PV GEMM, causal)
// ---------------------------------------------------------------------------
template <bool TRANS_B, bool CAUSAL_SKIP, bool KLIMIT>
__global__ void __launch_bounds__(256, 2)
gemm_k(const float* __restrict__ A, const float* __restrict__ Bm,
       float* __restrict__ C,
       int M, int N, int K, int lda, int ldb, int ldc,
       long sA, long sB, long sC)
{
    const int m0 = blockIdx.y * 64;
    const int n0 = blockIdx.x * 128;
    if (CAUSAL_SKIP && n0 > m0 + 63) return;

    A  += (long)blockIdx.z * sA;
    Bm += (long)blockIdx.z * sB;
    C  += (long)blockIdx.z * sC;

    int Keff = K;
    if (KLIMIT) Keff = min(K, m0 + 64);
    const int nkt = Keff >> 4;   // K / 16

    constexpr int BROWS = TRANS_B ? 128 : 16;
    constexpr int BLD   = TRANS_B ? 20  : 136;

    __shared__ __align__(16) float As[2][64][20];
    __shared__ __align__(16) float Bs[2][BROWS][BLD];

    const int tid  = threadIdx.x;
    const int warp = tid >> 5;
    const int lane = tid & 31;
    const int wm   = warp >> 2;   // 0..1
    const int wn   = warp & 3;    // 0..3

    // A loader: 64x16 tile = 256 float4, 1 per thread
    const int ar = tid >> 2;
    const int ac = (tid & 3) * 4;

    auto load_stage = [&](int st, int kt) {
        const int k0 = kt << 4;
        cp_async16(&As[st][ar][ac], A + (long)(m0 + ar) * lda + k0 + ac);
        if (TRANS_B) {
            // B tile 128 x 16 (rows = n), like A
            #pragma unroll
            for (int i = 0; i < 2; i++) {
                int idx = tid + 256 * i;
                int r = idx >> 2, c = (idx & 3) * 4;
                cp_async16(&Bs[st][r][c], Bm + (long)(n0 + r) * ldb + k0 + c);
            }
        } else {
            // B tile 16 x 128 (rows = k)
            #pragma unroll
            for (int i = 0; i < 2; i++) {
                int idx = tid + 256 * i;
                int r = idx >> 5, c = (idx & 31) * 4;
                cp_async16(&Bs[st][r][c], Bm + (long)(k0 + r) * ldb + n0 + c);
            }
        }
        cp_commit();
    };

    float acc[2][4][4] = {};

    load_stage(0, 0);
    for (int kt = 0; kt < nkt; ++kt) {
        const int cur = kt & 1;
        if (kt + 1 < nkt) { load_stage(cur ^ 1, kt + 1); cp_wait1(); }
        else              { cp_wait0(); }
        __syncthreads();

        #pragma unroll
        for (int kk = 0; kk < 16; kk += 8) {
            uint32_t af[2][4], bf[4][2];
            #pragma unroll
            for (int mi = 0; mi < 2; mi++) {
                const int rb = wm * 32 + mi * 16 + (lane >> 2);
                const int cb = kk + (lane & 3);
                af[mi][0] = f2tf32(As[cur][rb][cb]);
                af[mi][1] = f2tf32(As[cur][rb + 8][cb]);
                af[mi][2] = f2tf32(As[cur][rb][cb + 4]);
                af[mi][3] = f2tf32(As[cur][rb + 8][cb + 4]);
            }
            #pragma unroll
            for (int ni = 0; ni < 4; ni++) {
                const int nb = wn * 32 + ni * 8 + (lane >> 2);
                if (TRANS_B) {
                    bf[ni][0] = f2tf32(Bs[cur][nb][kk + (lane & 3)]);
                    bf[ni][1] = f2tf32(Bs[cur][nb][kk + (lane & 3) + 4]);
                } else {
                    bf[ni][0] = f2tf32(Bs[cur][kk + (lane & 3)][nb]);
                    bf[ni][1] = f2tf32(Bs[cur][kk + (lane & 3) + 4][nb]);
                }
            }
            #pragma unroll
            for (int mi = 0; mi < 2; mi++)
                #pragma unroll
                for (int ni = 0; ni < 4; ni++)
                    mma_tf32(acc[mi][ni], af[mi], bf[ni]);
        }
        __syncthreads();
    }

    // Epilogue
    #pragma unroll
    for (int mi = 0; mi < 2; mi++) {
        #pragma unroll
        for (int ni = 0; ni < 4; ni++) {
            const int r0 = m0 + wm * 32 + mi * 16 + (lane >> 2);
            const int c0 = n0 + wn * 32 + ni * 8 + 2 * (lane & 3);
            *(float2*)&C[(long)r0 * ldc + c0] =
                make_float2(acc[mi][ni][0], acc[mi][ni][1]);
            *(float2*)&C[(long)(r0 + 8) * ldc + c0] =
                make_float2(acc[mi][ni][2], acc[mi][ni][3]);
        }
    }
}

// ---------------------------------------------------------------------------
// In-place causal row softmax over scores with logits s/32 (d_k = 1024).
// One block of 256 threads per row.  Writes zeros for j > i.
// ---------------------------------------------------------------------------
__global__ void __launch_bounds__(256)
softmax_k(float* __restrict__ P)
{
    const int row = blockIdx.x;        // 0 .. Bsz*Sq-1
    const int b = row >> 11;
    const int i = row & 2047;
    float* p = P + ((long)b * Sq + i) * Sq;
    const int tid = threadIdx.x;
    const int len = i + 1;

    float v[8];
    int cnt = 0;
    for (int j = tid; j < len; j += 256) v[cnt++] = p[j];

    float mx = -3.4e38f;
    #pragma unroll
    for (int c = 0; c < 8; c++) if (c < cnt) mx = fmaxf(mx, v[c]);
    mx = warp_max(mx);

    __shared__ float red[8];
    if ((tid & 31) == 0) red[tid >> 5] = mx;
    __syncthreads();
    mx = red[0];
    #pragma unroll
    for (int w = 1; w < 8; w++) mx = fmaxf(mx, red[w]);

    float s = 0.f;
    #pragma unroll
    for (int c = 0; c < 8; c++) {
        if (c < cnt) { v[c] = __expf((v[c] - mx) * 0.03125f); s += v[c]; }
    }
    s = warp_sum(s);
    __syncthreads();
    if ((tid & 31) == 0) red[tid >> 5] = s;
    __syncthreads();
    float tot = 0.f;
    #pragma unroll
    for (int w = 0; w < 8; w++) tot += red[w];
    const float inv = 1.0f / tot;

    cnt = 0;
    for (int j = tid; j < Sq; j += 256) {
        p[j] = (j < len) ? v[cnt++] * inv : 0.0f;
    }
}

// ---------------------------------------------------------------------------
extern "C" void kernel_launch(void* const* d_in, const int* in_sizes, int n_in,
                              void* d_out, int out_size)
{
    const float* x  = (const float*)d_in[0];
    const float* Wq = (const float*)d_in[1];
    const float* Wk = (const float*)d_in[2];
    const float* Wv = (const float*)d_in[3];
    float* out = (float*)d_out;

    float *Q, *K, *V, *P;
    cudaGetSymbolAddress((void**)&Q, g_Q);
    cudaGetSymbolAddress((void**)&K, g_K);
    cudaGetSymbolAddress((void**)&V, g_V);
    cudaGetSymbolAddress((void**)&P, g_P);

    const dim3 blk(256);
    const int M = Bsz * Sq;   // 8192

    // 1) Projections: Q = x Wq, K = x Wk, V = x Wv   (NN GEMMs)
    {
        dim3 grid(Dm / 128, M / 64, 1);
        gemm_k<false, false, false><<<grid, blk>>>(x, Wq, Q, M, Dm, Dm, Dm, Dm, Dm, 0, 0, 0);
        gemm_k<false, false, false><<<grid, blk>>>(x, Wk, K, M, Dm, Dm, Dm, Dm, Dm, 0, 0, 0);
        gemm_k<false, false, false><<<grid, blk>>>(x, Wv, V, M, Dm, Dm, Dm, Dm, Dm, 0, 0, 0);
    }

    // 2) Scores: S_b = Q_b K_b^T   (NT, causal-skip upper tiles)
    {
        dim3 grid(Sq / 128, Sq / 64, Bsz);
        gemm_k<true, true, false><<<grid, blk>>>(
            Q, K, P, Sq, Sq, Dm, Dm, Dm, Sq,
            (long)Sq * Dm, (long)Sq * Dm, (long)Sq * Sq);
    }

    // 3) Softmax (in place, causal, scale 1/32)
    softmax_k<<<Bsz * Sq, 256>>>(P);

    // 4) O = P V   (NN, K-loop limited by causality)
    {
        dim3 grid(Dm / 128, Sq / 64, Bsz);
        gemm_k<false, false, true><<<grid, blk>>>(
            P, V, out, Sq, Dm, Sq, Sq, Dm, Dm,
            (long)Sq * Sq, (long)Sq * Dm, (long)Sq * Dm);
    }

    (void)in_sizes; (void)n_in; (void)out_size;
}